// round 17
// baseline (speedup 1.0000x reference)
#include <cuda_runtime.h>
#include <math.h>

#define BN 32768
#define DN 1024
#define CN 256
#define MAXM 640          // max members/class (mean 128, sd ~11.3; 640 unreachable)
#define NCHUNK 128        // 32768 / 256
#define NSPL 8            // splits per class
#define NBLK (CN * NSPL)  // k_mega grid

// Scratch — overwritten every launch where read; counters self-reset (replay safe).
__device__ __align__(16) float g_invnorm[BN];
__device__ __align__(16) int   g_order[CN * MAXM];
__device__ __align__(16) int   g_counts[CN];
__device__ __align__(16) int   g_hist[CN * NCHUNK];   // TRANSPOSED: [class][chunk]
__device__ __align__(16) float g_sumsP[NSPL][CN * DN];
__device__ __align__(16) float g_partial[CN];
__device__ int g_sem1;               // k_build phase barrier
__device__ int g_sem2;               // k_build reset barrier
__device__ int g_done_cls[CN];       // per-class split completion counters
__device__ int g_sem;                // k_mega final-reduce barrier

// Second-read load (defeats CSE; pass-1 row regs die across the norm reduce).
__device__ __forceinline__ float4 ldg_ca4(const float4* p) {
    float4 v;
    asm volatile("ld.global.ca.v4.f32 {%0,%1,%2,%3}, [%4];"
                 : "=f"(v.x), "=f"(v.y), "=f"(v.z), "=f"(v.w) : "l"(p));
    return v;
}

// ---------------- K_build: hist + scan + rank fused (one launch) ---------------------
// 128 blocks, all co-resident -> internal spin barrier is safe.
__global__ void __launch_bounds__(256) k_build(const int* __restrict__ labels) {
    __shared__ int h[CN];
    __shared__ int cb[CN];
    __shared__ int wcnt[8 * CN];
    int tid = threadIdx.x, lane = tid & 31, wid = tid >> 5;
    int chunk = blockIdx.x;

    // Phase 1: chunk histogram (smem int atomics -> deterministic counts)
    h[tid] = 0;
    #pragma unroll
    for (int i = 0; i < 8; i++) wcnt[i * 256 + tid] = 0;
    int j = chunk * 256 + tid;
    int lab = labels[j];
    __syncthreads();
    atomicAdd(&h[lab], 1);
    __syncthreads();
    g_hist[tid * NCHUNK + chunk] = h[tid];          // transposed store
    __threadfence();
    if (tid == 0) {
        atomicAdd(&g_sem1, 1);
        while (*(volatile int*)&g_sem1 < NCHUNK) { }
    }
    __syncthreads();
    __threadfence();

    // Phase 2: per-class exclusive prefix for THIS chunk (thread t = class t).
    // Transposed layout -> per-thread SEQUENTIAL reads (L2/L1 line reuse).
    int base = 0;
    {
        const int* __restrict__ hrow = g_hist + tid * NCHUNK;
        int b = 0;
        for (; b + 4 <= chunk; b += 4) {
            int v0 = hrow[b], v1 = hrow[b+1], v2 = hrow[b+2], v3 = hrow[b+3];
            base += v0 + v1 + v2 + v3;
        }
        for (; b < chunk; b++) base += hrow[b];
    }
    cb[tid] = base;
    if (chunk == NCHUNK - 1) g_counts[tid] = base + h[tid];
    __syncthreads();

    // Phase 3: within-chunk stable rank via match_any + per-warp class counts
    unsigned mm = __match_any_sync(0xffffffffu, lab);
    int wrank = __popc(mm & ((1u << lane) - 1u));
    if (wrank == 0) wcnt[wid * CN + lab] = __popc(mm);   // group leader posts count
    __syncthreads();
    int rank = wrank;
    for (int w = 0; w < wid; w++) rank += wcnt[w * CN + lab];
    int pos = cb[lab] + rank;
    if (pos < MAXM) g_order[lab * MAXM + pos] = j;

    // Reset counters for next replay (last block to finish)
    __threadfence();
    if (tid == 0) {
        if (atomicAdd(&g_sem2, 1) == NCHUNK - 1) { g_sem1 = 0; g_sem2 = 0; }
    }
}

// Block reduce helper: sums 'v' over 256 threads; result valid on tid 0.
__device__ __forceinline__ float blk_sum(float v, float* ws, int lane, int wid) {
    #pragma unroll
    for (int o = 16; o; o >>= 1) v += __shfl_xor_sync(0xffffffffu, v, o);
    if (lane == 0) ws[wid] = v;
    __syncthreads();
    float t = 0.f;
    if (wid == 0) {
        t = (lane < 8) ? ws[lane] : 0.f;
        #pragma unroll
        for (int o = 4; o; o >>= 1) t += __shfl_xor_sync(0xffffffffu, t, o);
    }
    __syncthreads();
    return t;  // valid on tid 0
}

// ---------------- K_mega: sums phase + per-class closed-form loss + global final -----
// grid = CN*8 (class c, split s). Leader = split 7 (highest bid -> peers earlier/equal
// wave -> near-zero spin). Corrections are warp-parallel with fixed-order summation.
__global__ void __launch_bounds__(256, 3) k_mega(const float* __restrict__ feat,
                                                 float* __restrict__ out) {
    int c = blockIdx.x >> 3;
    int s = blockIdx.x & 7;
    int tid = threadIdx.x, lane = tid & 31, wid = tid >> 5;
    __shared__ float4 st4[8 * (DN / 4)];

    int n = g_counts[c];
    int n_eff = (n < MAXM) ? n : MAXM;
    const int* __restrict__ ord = g_order + c * MAXM;
    const float4* __restrict__ f4 = (const float4*)feat;

    // ================= sums phase: warp-per-row, two-pass read =================
    float4 acc[8];
    #pragma unroll
    for (int k = 0; k < 8; k++) acc[k] = make_float4(0.f, 0.f, 0.f, 0.f);

    int gw = s * 8 + wid;           // 0..63
    for (int r = gw; r < n_eff; r += 64) {
        int m0 = ord[r];
        const float4* row0 = f4 + (size_t)m0 * (DN / 4);

        float s0 = 0.f;
        {
            float4 v[8];
            #pragma unroll
            for (int k = 0; k < 8; k++) v[k] = row0[k * 32 + lane];
            #pragma unroll
            for (int k = 0; k < 8; k++)
                s0 += v[k].x*v[k].x + v[k].y*v[k].y + v[k].z*v[k].z + v[k].w*v[k].w;
        }
        #pragma unroll
        for (int o = 16; o; o >>= 1) s0 += __shfl_xor_sync(0xffffffffu, s0, o);
        float i0 = rsqrtf(fmaxf(s0, 1e-24f));
        if (lane == 0) g_invnorm[m0] = i0;

        #pragma unroll
        for (int k = 0; k < 8; k++) {
            float4 v = ldg_ca4(row0 + k * 32 + lane);
            acc[k].x += v.x * i0; acc[k].y += v.y * i0;
            acc[k].z += v.z * i0; acc[k].w += v.w * i0;
        }
    }

    #pragma unroll
    for (int k = 0; k < 8; k++) st4[wid * (DN / 4) + k * 32 + lane] = acc[k];
    __syncthreads();
    {
        float4 t = st4[tid];
        #pragma unroll
        for (int w = 1; w < 8; w++) {
            float4 u = st4[w * (DN / 4) + tid];
            t.x += u.x; t.y += u.y; t.z += u.z; t.w += u.w;
        }
        ((float4*)g_sumsP[s])[c * (DN / 4) + tid] = t;
    }
    __threadfence();
    __syncthreads();
    if (tid == 0) atomicAdd(&g_done_cls[c], 1);
    if (s != NSPL - 1) return;

    // ================= leader (split 7): wait peers, then class loss =================
    if (tid == 0) {
        while (*(volatile int*)&g_done_cls[c] < NSPL) { }
    }
    __syncthreads();
    __threadfence();

    __shared__ float ws[8];
    __shared__ float bc[1];
    __shared__ int   lst[64];
    __shared__ float corrv[64];
    __shared__ int   ncorr;
    __shared__ int   amLast;

    // Combine 8 split partials -> S; stage full S in smem (reuse st4[0..255])
    float4 sv = make_float4(0.f, 0.f, 0.f, 0.f);
    #pragma unroll
    for (int p = 0; p < NSPL; p++) {
        float4 u = ((const float4*)g_sumsP[p])[c * (DN/4) + tid];
        sv.x += u.x; sv.y += u.y; sv.z += u.z; sv.w += u.w;
    }
    st4[tid] = sv;                         // smem-resident S for warp-parallel dots
    float q = sv.x*sv.x + sv.y*sv.y + sv.z*sv.z + sv.w*sv.w;
    float Q = blk_sum(q, ws, lane, wid);   // includes __syncthreads (st4 visible after)
    if (tid == 0) bc[0] = Q;
    if (tid == 0) {
        // build exclusion list: members with global index < n (ord ascending -> break)
        int m = 0;
        for (int rr = 0; rr < n_eff && m < 64; rr++) {
            int i = ord[rr];
            if (i >= n) break;
            lst[m++] = i;
        }
        ncorr = (n > 1) ? m : 0;
    }
    __syncthreads();
    Q = bc[0];
    int m = ncorr;

    // warp-parallel corrections (each warp: 3 dot products + shfl reduce)
    float fn = (float)n, nm1 = fn - 1.0f;
    for (int e = wid; e < m; e += 8) {
        int i  = lst[e];
        int k2 = ord[i];
        float pa = 0.f, pb = 0.f, pd = 0.f;
        const float4* rowi = f4 + (size_t)i  * (DN/4);
        const float4* rowk = f4 + (size_t)k2 * (DN/4);
        #pragma unroll
        for (int kk = 0; kk < 8; kk++) {
            float4 va = rowi[kk * 32 + lane];
            float4 vk = rowk[kk * 32 + lane];
            float4 sS = st4[kk * 32 + lane];
            pa += va.x*sS.x + va.y*sS.y + va.z*sS.z + va.w*sS.w;
            pb += va.x*vk.x + va.y*vk.y + va.z*vk.z + va.w*vk.w;
            pd += sS.x*vk.x + sS.y*vk.y + sS.z*vk.z + sS.w*vk.w;
        }
        #pragma unroll
        for (int o = 16; o; o >>= 1) {
            pa += __shfl_xor_sync(0xffffffffu, pa, o);
            pb += __shfl_xor_sync(0xffffffffu, pb, o);
            pd += __shfl_xor_sync(0xffffffffu, pd, o);
        }
        if (lane == 0) {
            float inv_i = g_invnorm[i], inv_k = g_invnorm[k2];
            float a = pa * inv_i;                 // f_i · S
            float b = pb * inv_i * inv_k;         // f_i · f_k
            float d = pd * inv_k;                 // S   · f_k
            float excl  = -2.0f * (a - b) / nm1 + (Q - 2.0f * d + 1.0f) / (nm1 * nm1);
            float plain = -2.0f * a / fn + Q / (fn * fn);
            corrv[e] = excl - plain;
        }
    }
    __syncthreads();

    if (tid == 0) {
        float raw = 0.f;
        if (n > 1) {
            raw = fn - Q / fn;                    // Σ||f_i − S/n||² with ||f_i||²=1
            for (int e = 0; e < m; e++) raw += corrv[e];   // fixed order
        }
        g_partial[c] = raw;
        __threadfence();
        amLast = (atomicAdd(&g_sem, 1) == CN - 1);
    }
    __syncthreads();
    if (amLast) {
        float v = g_partial[tid];
        float T = blk_sum(v, ws, lane, wid);
        g_done_cls[tid] = 0;                      // reset for next replay
        if (tid == 0) {
            out[0] = 0.0005f * T / ((float)BN * (float)DN);
            g_sem = 0;
        }
    }
}

extern "C" void kernel_launch(void* const* d_in, const int* in_sizes, int n_in,
                              void* d_out, int out_size) {
    const float* feat  = (const float*)d_in[0];
    const int*  labels = (const int*)d_in[1];
    float* out = (float*)d_out;
    (void)in_sizes; (void)n_in; (void)out_size;

    k_build<<<NCHUNK, 256>>>(labels);
    k_mega <<<NBLK, 256>>>(feat, out);
}